// round 7
// baseline (speedup 1.0000x reference)
#include <cuda_runtime.h>
#include <math.h>

typedef unsigned long long u64;

#define NB   8
#define HWI  256
#define OUTD 9490
#define WBASE_B 9376   // bias region start in flat

// ---------------- packed f32x2 helpers ----------------
__device__ __forceinline__ u64 pack2(float lo, float hi){
    u64 r; asm("mov.b64 %0,{%1,%2};" : "=l"(r) : "f"(lo), "f"(hi)); return r;
}
__device__ __forceinline__ u64 dup2f(float v){
    u64 r; asm("mov.b64 %0,{%1,%1};" : "=l"(r) : "f"(v)); return r;
}
__device__ __forceinline__ void ffma2(u64 &d, u64 a, u64 b){
    asm("fma.rn.f32x2 %0,%1,%2,%3;" : "=l"(d) : "l"(a), "l"(b), "l"(d));
}
__device__ __forceinline__ void unpack2(u64 v, float &lo, float &hi){
    asm("mov.b64 {%0,%1},%2;" : "=f"(lo), "=f"(hi) : "l"(v));
}

// ---------------- static device scratch ----------------
__device__ float g_h1[NB*100];
__device__ float g_h2[NB*1000];
__device__ float g_ha[NB*10000];
__device__ float g_hb[NB*10000];
__device__ float g_flat[NB*OUTD];

__device__ float g_t0[NB*256*256*8];
__device__ float g_c1[NB*256*256*8];
__device__ float g_p1[NB*128*128*8];
__device__ float g_t1[NB*128*128*8];
__device__ float g_c2[NB*128*128*8];
__device__ float g_p2[NB*64*64*8];
__device__ float g_t2[NB*64*64*8];
__device__ float g_c3[NB*64*64*8];
__device__ float g_p3[NB*32*32*8];
__device__ float g_t3[NB*32*32*8];
__device__ float g_c4[NB*32*32*8];
__device__ float g_u3[NB*64*64*16];
__device__ float g_v3[NB*64*64*8];
__device__ float g_w3[NB*64*64*8];
__device__ float g_u2[NB*128*128*16];
__device__ float g_v2[NB*128*128*8];
__device__ float g_w2[NB*128*128*8];
__device__ float g_u1[NB*256*256*16];
__device__ float g_v1[NB*256*256*8];
__device__ float g_w1[NB*256*256*8];

// ---------------- small FC (layers 1, 2) ----------------
__global__ void fc_small(const float* __restrict__ in, const float* __restrict__ W,
                         const float* __restrict__ bias, float* __restrict__ out,
                         int K, int J)
{
    int t = blockIdx.x * blockDim.x + threadIdx.x;
    if (t >= NB * J) return;
    int b = t / J, j = t - b * J;
    const float* w = W + (size_t)j * K;
    const float* x = in + (size_t)b * K;
    float s = bias[j];
    for (int k = 0; k < K; k++) s += x[k] * w[k];
    out[t] = s > 0.f ? s : 0.01f * s;
}

// ---------------- big FC (layers 3,4,5,out) ----------------
// out[b][j] = act( sum_k in[b][k] * W[j][k] + bias[j] ), B = 8 fixed.
// Warp owns 2 neurons (j0, j1); lane l owns k-quads starting at 4*l.
// All loads 128-bit: W via LDG.128 (ulonglong2), h via LDS.128 (ulonglong2).
// f32x2 halves come straight out of the vector registers — zero packing.
// Inner loop stride 256 k/warp with 4 LDG.128 batched up front (2KB in flight
// per warp) for memory-level parallelism.
#define FCB_CH 1536
__global__ __launch_bounds__(256, 3)
void fc_big(const float* __restrict__ in, const float* __restrict__ W,
            const float* __restrict__ bias, float* __restrict__ out,
            int K, int J, int act)
{
    __shared__ __align__(16) float hs[8 * FCB_CH];   // [b][chunk_k] 48 KB
    int tid  = threadIdx.x;
    int lane = tid & 31, warp = tid >> 5;
    int jbase = blockIdx.x * 16 + warp * 2;
    int j0 = min(jbase,     J - 1);
    int j1 = min(jbase + 1, J - 1);
    const float* W0 = W + (size_t)j0 * K;
    const float* W1 = W + (size_t)j1 * K;

    u64 acc[2][8];
    #pragma unroll
    for (int n = 0; n < 2; n++)
        #pragma unroll
        for (int b = 0; b < 8; b++) acc[n][b] = 0ULL;

    for (int cb = 0; cb < K; cb += FCB_CH) {
        int clen = min(FCB_CH, K - cb);
        int padlen = (clen + 255) & ~255;
        __syncthreads();
        #pragma unroll
        for (int b = 0; b < 8; b++)
            for (int r = tid; r < padlen; r += 256)
                hs[b * FCB_CH + r] = (r < clen) ? in[b * K + cb + r] : 0.f;
        __syncthreads();

        for (int kk = lane * 4; kk < padlen; kk += 256) {
            int k2 = kk + 128;
            int ka = min(cb + kk, K - 4);
            int kb = min(cb + k2, K - 4);
            ulonglong2 wa0 = __ldg((const ulonglong2*)(W0 + ka));
            ulonglong2 wb0 = __ldg((const ulonglong2*)(W0 + kb));
            ulonglong2 wa1 = __ldg((const ulonglong2*)(W1 + ka));
            ulonglong2 wb1 = __ldg((const ulonglong2*)(W1 + kb));
            #pragma unroll
            for (int b = 0; b < 8; b++) {
                ulonglong2 h = *(const ulonglong2*)&hs[b * FCB_CH + kk];
                ffma2(acc[0][b], wa0.x, h.x);
                ffma2(acc[0][b], wa0.y, h.y);
                ffma2(acc[1][b], wa1.x, h.x);
                ffma2(acc[1][b], wa1.y, h.y);
            }
            if (k2 < padlen) {
                #pragma unroll
                for (int b = 0; b < 8; b++) {
                    ulonglong2 h = *(const ulonglong2*)&hs[b * FCB_CH + k2];
                    ffma2(acc[0][b], wb0.x, h.x);
                    ffma2(acc[0][b], wb0.y, h.y);
                    ffma2(acc[1][b], wb1.x, h.x);
                    ffma2(acc[1][b], wb1.y, h.y);
                }
            }
        }
    }

    float red[2][8];
    #pragma unroll
    for (int n = 0; n < 2; n++)
        #pragma unroll
        for (int b = 0; b < 8; b++) {
            float e, o;
            unpack2(acc[n][b], e, o);
            float s = e + o;
            #pragma unroll
            for (int sh = 16; sh > 0; sh >>= 1) s += __shfl_xor_sync(0xffffffffu, s, sh);
            red[n][b] = s;
        }
    if (lane == 0) {
        #pragma unroll
        for (int n = 0; n < 2; n++) {
            int j = jbase + n;
            if (j >= J) break;
            float bb = bias[j];
            #pragma unroll
            for (int b = 0; b < 8; b++) {
                float s = red[n][b] + bb;
                if (act) s = s > 0.f ? s : 0.01f * s;
                out[b * J + j] = s;
            }
        }
    }
}

// ---------------- L1 of generated params ----------------
__global__ void l1norm(const float* __restrict__ flat, float* __restrict__ dout, int off)
{
    int b = blockIdx.x, tid = threadIdx.x;
    float s = 0.f;
    for (int j = tid; j < OUTD; j += 256) s += fabsf(flat[b * OUTD + j]);
    #pragma unroll
    for (int o = 16; o > 0; o >>= 1) s += __shfl_xor_sync(0xffffffffu, s, o);
    __shared__ float sm[8];
    if ((tid & 31) == 0) sm[tid >> 5] = s;
    __syncthreads();
    if (tid < 32) {
        float v = (tid < 8) ? sm[tid] : 0.f;
        #pragma unroll
        for (int o = 4; o > 0; o >>= 1) v += __shfl_xor_sync(0xffffffffu, v, o);
        if (tid == 0) dout[off + b] = v;
    }
}

// ---------------- 3x3 per-sample conv, COUT=8, NHWC, pad=1, relu ----------------
template<int CIN>
__global__ __launch_bounds__(256)
void conv3x3(const float* __restrict__ in, float* __restrict__ out,
             const float* __restrict__ flat, int woff, int boff, int H, int W)
{
    __shared__ __align__(16) float ws[CIN * 72];
    __shared__ float bs[8];
    __shared__ float tile[CIN][10][34];

    int b = blockIdx.z;
    const float* fb = flat + (size_t)b * OUTD;
    int tid = threadIdx.y * 32 + threadIdx.x;

    for (int idx = tid; idx < CIN * 72; idx += 256) {
        int o = idx & 7, it = idx >> 3;
        int i = it / 9, t = it - i * 9;
        ws[idx] = fb[woff + (o * CIN + i) * 9 + t];
    }
    if (tid < 8) bs[tid] = fb[boff + tid];

    int x0 = blockIdx.x * 32 - 1, y0 = blockIdx.y * 8 - 1;
    for (int idx = tid; idx < 340; idx += 256) {
        int yy = idx / 34, xx = idx - yy * 34;
        int gx = x0 + xx, gy = y0 + yy;
        bool inb = ((unsigned)gx < (unsigned)W) && ((unsigned)gy < (unsigned)H);
        if (inb) {
            const float* p = in + (((size_t)b * H + gy) * W + gx) * CIN;
            if (CIN == 2) {
                float2 q = *(const float2*)p;
                tile[0][yy][xx] = q.x;
                tile[1][yy][xx] = q.y;
            } else {
                #pragma unroll
                for (int c4 = 0; c4 < CIN; c4 += 4) {
                    float4 q = *(const float4*)(p + c4);
                    tile[c4 + 0][yy][xx] = q.x;
                    tile[c4 + 1][yy][xx] = q.y;
                    tile[c4 + 2][yy][xx] = q.z;
                    tile[c4 + 3][yy][xx] = q.w;
                }
            }
        } else {
            #pragma unroll
            for (int c = 0; c < CIN; c++) tile[c][yy][xx] = 0.f;
        }
    }
    __syncthreads();

    int tx = threadIdx.x, ty = threadIdx.y;
    u64 acc[4];
    #pragma unroll
    for (int p = 0; p < 4; p++) acc[p] = pack2(bs[2 * p], bs[2 * p + 1]);

    const u64* wsu = (const u64*)ws;
    #pragma unroll
    for (int i = 0; i < CIN; i++) {
        #pragma unroll
        for (int ky = 0; ky < 3; ky++)
            #pragma unroll
            for (int kx = 0; kx < 3; kx++) {
                u64 v = dup2f(tile[i][ty + ky][tx + kx]);
                int t = ky * 3 + kx;
                #pragma unroll
                for (int p = 0; p < 4; p++) ffma2(acc[p], v, wsu[(i * 9 + t) * 4 + p]);
            }
    }

    int gx = blockIdx.x * 32 + tx, gy = blockIdx.y * 8 + ty;
    if (gx >= W || gy >= H) return;
    float o_[8];
    #pragma unroll
    for (int p = 0; p < 4; p++) unpack2(acc[p], o_[2 * p], o_[2 * p + 1]);
    #pragma unroll
    for (int c = 0; c < 8; c++) o_[c] = fmaxf(o_[c], 0.f);
    float* po = out + (((size_t)b * H + gy) * W + gx) * 8;
    *(float4*)(po)     = make_float4(o_[0], o_[1], o_[2], o_[3]);
    *(float4*)(po + 4) = make_float4(o_[4], o_[5], o_[6], o_[7]);
}

// ---------------- 2x2 maxpool, NHWC C=8 ----------------
__device__ __forceinline__ float4 fmax4(float4 a, float4 b){
    return make_float4(fmaxf(a.x,b.x), fmaxf(a.y,b.y), fmaxf(a.z,b.z), fmaxf(a.w,b.w));
}
__global__ void maxpool2(const float* __restrict__ in, float* __restrict__ out, int Ho, int Wo)
{
    int idx = blockIdx.x * 256 + threadIdx.x;
    int total = NB * Ho * Wo;
    if (idx >= total) return;
    int x = idx % Wo; int r = idx / Wo; int y = r % Ho; int b = r / Ho;
    int Hi = 2 * Ho, Wi = 2 * Wo;
    const float4* p00 = (const float4*)(in + (((size_t)b * Hi + 2 * y) * Wi + 2 * x) * 8);
    const float4* p10 = (const float4*)(in + (((size_t)b * Hi + 2 * y + 1) * Wi + 2 * x) * 8);
    float4 a0 = fmax4(fmax4(p00[0], p00[2]), fmax4(p10[0], p10[2]));
    float4 a1 = fmax4(fmax4(p00[1], p00[3]), fmax4(p10[1], p10[3]));
    float* po = out + (((size_t)b * Ho + y) * Wo + x) * 8;
    *(float4*)(po)     = a0;
    *(float4*)(po + 4) = a1;
}

// ------- bilinear x2 (align_corners) upsample of sm (8ch) + concat skip (8ch) -------
__global__ void upcat(const float* __restrict__ sm, const float* __restrict__ skip,
                      float* __restrict__ out, int Hs, int Ws)
{
    int Ho = 2 * Hs, Wo = 2 * Ws;
    int idx = blockIdx.x * 256 + threadIdx.x;
    int total = NB * Ho * Wo;
    if (idx >= total) return;
    int x = idx % Wo; int r = idx / Wo; int y = r % Ho; int b = r / Ho;

    float fy = y * ((float)(Hs - 1) / (float)(Ho - 1));
    float fx = x * ((float)(Ws - 1) / (float)(Wo - 1));
    int y0 = (int)fy, x0 = (int)fx;
    int y1 = min(y0 + 1, Hs - 1), x1 = min(x0 + 1, Ws - 1);
    float ty = fy - (float)y0, tx = fx - (float)x0;
    float w00 = (1.f - ty) * (1.f - tx), w01 = (1.f - ty) * tx;
    float w10 = ty * (1.f - tx),         w11 = ty * tx;

    const float* p00 = sm + (((size_t)b * Hs + y0) * Ws + x0) * 8;
    const float* p01 = sm + (((size_t)b * Hs + y0) * Ws + x1) * 8;
    const float* p10 = sm + (((size_t)b * Hs + y1) * Ws + x0) * 8;
    const float* p11 = sm + (((size_t)b * Hs + y1) * Ws + x1) * 8;
    float* po = out + (((size_t)b * Ho + y) * Wo + x) * 16;
    #pragma unroll
    for (int c = 0; c < 8; c++)
        po[c] = w00 * p00[c] + w01 * p01[c] + w10 * p10[c] + w11 * p11[c];
    const float* ps = skip + (((size_t)b * Ho + y) * Wo + x) * 8;
    *(float4*)(po + 8)  = *(const float4*)ps;
    *(float4*)(po + 12) = *(const float4*)(ps + 4);
}

// ---------------- final 1x1 conv (8->2) + residual with zf ----------------
// w14 at flat offset 9360 (shape (2,8)), b14 at 9488.
__global__ void conv1x1_res(const float* __restrict__ in, const float* __restrict__ zf,
                            const float* __restrict__ flat, float* __restrict__ out)
{
    int idx = blockIdx.x * 256 + threadIdx.x;
    int total = NB * HWI * HWI;
    if (idx >= total) return;
    int b = idx / (HWI * HWI);
    const float* fb = flat + (size_t)b * OUTD;
    const float* p = in + (size_t)idx * 8;
    float4 a = *(const float4*)p, c = *(const float4*)(p + 4);
    float v[8] = {a.x, a.y, a.z, a.w, c.x, c.y, c.z, c.w};
    float o0 = fb[9488], o1 = fb[9489];          // b14
    #pragma unroll
    for (int i = 0; i < 8; i++) {
        o0 += fb[9360 + i]     * v[i];           // w14[0][i]
        o1 += fb[9360 + 8 + i] * v[i];           // w14[1][i]
    }
    float2 z = *(const float2*)(zf + (size_t)idx * 2);
    float2 r = make_float2(z.x + o0, z.y + o1);
    *(float2*)(out + (size_t)idx * 2) = r;
}

// ---------------- launcher ----------------
static float* sym(const void* s) {
    void* p = nullptr;
    cudaGetSymbolAddress(&p, s);
    return (float*)p;
}

extern "C" void kernel_launch(void* const* d_in, const int* in_sizes, int n_in,
                              void* d_out, int out_size)
{
    const float* zf  = (const float*)d_in[0];
    const float* hyp = (const float*)d_in[2];
    const float* hw1 = (const float*)d_in[3];  const float* hb1 = (const float*)d_in[4];
    const float* hw2 = (const float*)d_in[5];  const float* hb2 = (const float*)d_in[6];
    const float* hw3 = (const float*)d_in[7];  const float* hb3 = (const float*)d_in[8];
    const float* hw4 = (const float*)d_in[9];  const float* hb4 = (const float*)d_in[10];
    const float* hw5 = (const float*)d_in[11]; const float* hb5 = (const float*)d_in[12];
    const float* hwo = (const float*)d_in[13]; const float* hbo = (const float*)d_in[14];
    float* dout = (float*)d_out;

    float *h1 = sym(g_h1), *h2 = sym(g_h2), *ha = sym(g_ha), *hb = sym(g_hb), *fl = sym(g_flat);
    float *t0 = sym(g_t0), *c1 = sym(g_c1), *p1 = sym(g_p1), *t1 = sym(g_t1), *c2 = sym(g_c2);
    float *p2 = sym(g_p2), *t2 = sym(g_t2), *c3 = sym(g_c3), *p3 = sym(g_p3), *t3 = sym(g_t3);
    float *c4 = sym(g_c4), *u3 = sym(g_u3), *v3 = sym(g_v3), *w3 = sym(g_w3);
    float *u2 = sym(g_u2), *v2 = sym(g_v2), *w2 = sym(g_w2);
    float *u1 = sym(g_u1), *v1 = sym(g_v1), *w1 = sym(g_w1);

    // ---- hypernetwork ----
    fc_small<<<(NB * 100 + 255) / 256, 256>>>(hyp, hw1, hb1, h1, 1, 100);
    fc_small<<<(NB * 1000 + 255) / 256, 256>>>(h1, hw2, hb2, h2, 100, 1000);
    fc_big<<<(10000 + 15) / 16, 256>>>(h2, hw3, hb3, ha, 1000, 10000, 1);
    fc_big<<<(10000 + 15) / 16, 256>>>(ha, hw4, hb4, hb, 10000, 10000, 1);
    fc_big<<<(10000 + 15) / 16, 256>>>(hb, hw5, hb5, ha, 10000, 10000, 1);
    fc_big<<<(OUTD  + 15) / 16, 256>>>(ha, hwo, hbo, fl, 10000, OUTD, 0);
    l1norm<<<NB, 256>>>(fl, dout, NB * HWI * HWI * 2);

    // ---- U-Net ----
    // weight offsets: w0=0 w1=144 w2=720 w3=1296 w4=1872 w5=2448 w6=3024 w7=3600
    //                 w8=4176 w9=5328 w10=5904 w11=7056 w12=7632 w13=8784 w14=9360
    dim3 blk(32, 8);
    dim3 g256(8, 32, NB), g128(4, 16, NB), g64(2, 8, NB), g32(1, 4, NB);

    conv3x3<2><<<g256, blk>>>(zf, t0, fl, 0,    WBASE_B + 0,   256, 256);
    conv3x3<8><<<g256, blk>>>(t0, c1, fl, 144,  WBASE_B + 8,   256, 256);
    maxpool2<<<(NB * 128 * 128 + 255) / 256, 256>>>(c1, p1, 128, 128);
    conv3x3<8><<<g128, blk>>>(p1, t1, fl, 720,  WBASE_B + 16,  128, 128);
    conv3x3<8><<<g128, blk>>>(t1, c2, fl, 1296, WBASE_B + 24,  128, 128);
    maxpool2<<<(NB * 64 * 64 + 255) / 256, 256>>>(c2, p2, 64, 64);
    conv3x3<8><<<g64, blk>>>(p2, t2, fl, 1872,  WBASE_B + 32,  64, 64);
    conv3x3<8><<<g64, blk>>>(t2, c3, fl, 2448,  WBASE_B + 40,  64, 64);
    maxpool2<<<(NB * 32 * 32 + 255) / 256, 256>>>(c3, p3, 32, 32);
    conv3x3<8><<<g32, blk>>>(p3, t3, fl, 3024,  WBASE_B + 48,  32, 32);
    conv3x3<8><<<g32, blk>>>(t3, c4, fl, 3600,  WBASE_B + 56,  32, 32);

    upcat<<<(NB * 64 * 64 + 255) / 256, 256>>>(c4, c3, u3, 32, 32);
    conv3x3<16><<<g64, blk>>>(u3, v3, fl, 4176, WBASE_B + 64,  64, 64);
    conv3x3<8><<<g64, blk>>>(v3, w3, fl, 5328,  WBASE_B + 72,  64, 64);

    upcat<<<(NB * 128 * 128 + 255) / 256, 256>>>(w3, c2, u2, 64, 64);
    conv3x3<16><<<g128, blk>>>(u2, v2, fl, 5904, WBASE_B + 80, 128, 128);
    conv3x3<8><<<g128, blk>>>(v2, w2, fl, 7056,  WBASE_B + 88, 128, 128);

    upcat<<<(NB * 256 * 256 + 255) / 256, 256>>>(w2, c1, u1, 128, 128);
    conv3x3<16><<<g256, blk>>>(u1, v1, fl, 7632, WBASE_B + 96, 256, 256);
    conv3x3<8><<<g256, blk>>>(v1, w1, fl, 8784,  WBASE_B + 104, 256, 256);

    conv1x1_res<<<(NB * HWI * HWI + 255) / 256, 256>>>(w1, zf, fl, dout);
}

// round 8
// speedup vs baseline: 1.2350x; 1.2350x over previous
#include <cuda_runtime.h>
#include <math.h>

typedef unsigned long long u64;

#define NB   8
#define HWI  256
#define OUTD 9490
#define WBASE_B 9376   // bias region start in flat

// ---------------- packed f32x2 helpers ----------------
__device__ __forceinline__ u64 pack2(float lo, float hi){
    u64 r; asm("mov.b64 %0,{%1,%2};" : "=l"(r) : "f"(lo), "f"(hi)); return r;
}
__device__ __forceinline__ u64 dup2f(float v){
    u64 r; asm("mov.b64 %0,{%1,%1};" : "=l"(r) : "f"(v)); return r;
}
__device__ __forceinline__ void ffma2(u64 &d, u64 a, u64 b){
    asm("fma.rn.f32x2 %0,%1,%2,%3;" : "=l"(d) : "l"(a), "l"(b), "l"(d));
}
__device__ __forceinline__ void unpack2(u64 v, float &lo, float &hi){
    asm("mov.b64 {%0,%1},%2;" : "=f"(lo), "=f"(hi) : "l"(v));
}

// ---------------- static device scratch ----------------
__device__ __align__(16) float g_h1[NB*100];
__device__ __align__(16) float g_h2[NB*1000];
__device__ __align__(16) float g_ha[NB*10000];
__device__ __align__(16) float g_hb[NB*10000];
__device__ __align__(16) float g_flat[NB*OUTD];

__device__ __align__(16) float g_t0[NB*256*256*8];
__device__ __align__(16) float g_c1[NB*256*256*8];
__device__ __align__(16) float g_p1[NB*128*128*8];
__device__ __align__(16) float g_t1[NB*128*128*8];
__device__ __align__(16) float g_c2[NB*128*128*8];
__device__ __align__(16) float g_p2[NB*64*64*8];
__device__ __align__(16) float g_t2[NB*64*64*8];
__device__ __align__(16) float g_c3[NB*64*64*8];
__device__ __align__(16) float g_p3[NB*32*32*8];
__device__ __align__(16) float g_t3[NB*32*32*8];
__device__ __align__(16) float g_c4[NB*32*32*8];
__device__ __align__(16) float g_u3[NB*64*64*16];
__device__ __align__(16) float g_v3[NB*64*64*8];
__device__ __align__(16) float g_w3[NB*64*64*8];
__device__ __align__(16) float g_u2[NB*128*128*16];
__device__ __align__(16) float g_v2[NB*128*128*8];
__device__ __align__(16) float g_w2[NB*128*128*8];
__device__ __align__(16) float g_u1[NB*256*256*16];
__device__ __align__(16) float g_v1[NB*256*256*8];
__device__ __align__(16) float g_w1[NB*256*256*8];

// ---------------- small FC (layers 1, 2) ----------------
__global__ void fc_small(const float* __restrict__ in, const float* __restrict__ W,
                         const float* __restrict__ bias, float* __restrict__ out,
                         int K, int J)
{
    int t = blockIdx.x * blockDim.x + threadIdx.x;
    if (t >= NB * J) return;
    int b = t / J, j = t - b * J;
    const float* w = W + (size_t)j * K;
    const float* x = in + (size_t)b * K;
    float s = bias[j];
    for (int k = 0; k < K; k++) s += x[k] * w[k];
    out[t] = s > 0.f ? s : 0.01f * s;
}

// ---------------- big FC (layers 3,4,5,out) ----------------
// out[b][j] = act( sum_k in[b][k] * W[j][k] + bias[j] ), B = 8 fixed.
// Warp owns 2 rows. Lane l owns k = l*4 + 128*t (LDG.128 per row per t).
// Depth-2 register ring on W: iteration t computes with W(t) while W(t+2)
// is in flight. h double-buffered in smem: chunk c+1 staged during chunk c's
// compute. W prefetch indices are global-k, so the pipeline crosses chunk
// boundaries (registers survive the barrier).
#define FCB_CH 768           // k per chunk (6 compute iterations of 128)
#define FCB_IT (FCB_CH/128)
__global__ __launch_bounds__(256, 3)
void fc_big(const float* __restrict__ in, const float* __restrict__ W,
            const float* __restrict__ bias, float* __restrict__ out,
            int K, int J, int act)
{
    __shared__ __align__(16) float hs[2][8 * FCB_CH];   // 2 x 24 KB
    int tid  = threadIdx.x;
    int lane = tid & 31, warp = tid >> 5;
    int jbase = blockIdx.x * 16 + warp * 2;
    int j0 = min(jbase,     J - 1);
    int j1 = min(jbase + 1, J - 1);
    const float* W0 = W + (size_t)j0 * K;
    const float* W1 = W + (size_t)j1 * K;

    int nchunk = (K + FCB_CH - 1) / FCB_CH;
    int iters  = nchunk * FCB_IT;

    u64 acc[2][8];
    #pragma unroll
    for (int n = 0; n < 2; n++)
        #pragma unroll
        for (int b = 0; b < 8; b++) acc[n][b] = 0ULL;

    // ---- stage chunk 0 ----
    {
        int clen = min(FCB_CH, K);
        #pragma unroll
        for (int b = 0; b < 8; b++) {
            int r = (tid % 192) * 4;       // 192 float4 per batch row
            int bb = b;                     // 8*192 = 1536 float4, 256 thr -> 6 each
            // distribute: thread covers (b, r) pairs via flat index
        }
        for (int idx = tid; idx < 8 * (FCB_CH / 4); idx += 256) {
            int b = idx / (FCB_CH / 4), r = (idx - b * (FCB_CH / 4)) * 4;
            float4 v = (r < clen) ? *(const float4*)&in[b * K + r]
                                  : make_float4(0.f, 0.f, 0.f, 0.f);
            *(float4*)&hs[0][b * FCB_CH + r] = v;
        }
    }

    // ---- preload W ring (slots 0,1) ----
    ulonglong2 w0r[2], w1r[2];
    {
        int kg0 = min(lane * 4,        K - 4);
        int kg1 = min(128 + lane * 4,  K - 4);
        w0r[0] = __ldg((const ulonglong2*)(W0 + kg0));
        w1r[0] = __ldg((const ulonglong2*)(W1 + kg0));
        w0r[1] = __ldg((const ulonglong2*)(W0 + kg1));
        w1r[1] = __ldg((const ulonglong2*)(W1 + kg1));
    }
    __syncthreads();

    for (int c = 0; c < nchunk; c++) {
        const float* hb = hs[c & 1];
        // stage next chunk into the other buffer (overlaps with compute)
        if (c + 1 < nchunk) {
            int cb = (c + 1) * FCB_CH;
            int clen = min(FCB_CH, K - cb);
            for (int idx = tid; idx < 8 * (FCB_CH / 4); idx += 256) {
                int b = idx / (FCB_CH / 4), r = (idx - b * (FCB_CH / 4)) * 4;
                float4 v = (r < clen) ? *(const float4*)&in[b * K + cb + r]
                                      : make_float4(0.f, 0.f, 0.f, 0.f);
                *(float4*)&hs[(c + 1) & 1][b * FCB_CH + r] = v;
            }
        }
        #pragma unroll
        for (int tt = 0; tt < FCB_IT; tt++) {
            int t = c * FCB_IT + tt;
            int s = tt & 1;                     // == t&1 (FCB_IT even)
            ulonglong2 w0 = w0r[s], w1 = w1r[s];
            if (t + 2 < iters) {                // prefetch distance 2
                int kg = min((t + 2) * 128 + lane * 4, K - 4);
                w0r[s] = __ldg((const ulonglong2*)(W0 + kg));
                w1r[s] = __ldg((const ulonglong2*)(W1 + kg));
            }
            const float* hp = hb + tt * 128 + lane * 4;
            #pragma unroll
            for (int b = 0; b < 8; b++) {
                ulonglong2 h = *(const ulonglong2*)(hp + b * FCB_CH);
                ffma2(acc[0][b], w0.x, h.x);
                ffma2(acc[0][b], w0.y, h.y);
                ffma2(acc[1][b], w1.x, h.x);
                ffma2(acc[1][b], w1.y, h.y);
            }
        }
        __syncthreads();
    }

    float red[2][8];
    #pragma unroll
    for (int n = 0; n < 2; n++)
        #pragma unroll
        for (int b = 0; b < 8; b++) {
            float e, o;
            unpack2(acc[n][b], e, o);
            float s = e + o;
            #pragma unroll
            for (int sh = 16; sh > 0; sh >>= 1) s += __shfl_xor_sync(0xffffffffu, s, sh);
            red[n][b] = s;
        }
    if (lane == 0) {
        #pragma unroll
        for (int n = 0; n < 2; n++) {
            int j = jbase + n;
            if (j >= J) break;
            float bb = bias[j];
            #pragma unroll
            for (int b = 0; b < 8; b++) {
                float s = red[n][b] + bb;
                if (act) s = s > 0.f ? s : 0.01f * s;
                out[b * J + j] = s;
            }
        }
    }
}

// ---------------- L1 of generated params ----------------
__global__ void l1norm(const float* __restrict__ flat, float* __restrict__ dout, int off)
{
    int b = blockIdx.x, tid = threadIdx.x;
    float s = 0.f;
    for (int j = tid; j < OUTD; j += 256) s += fabsf(flat[b * OUTD + j]);
    #pragma unroll
    for (int o = 16; o > 0; o >>= 1) s += __shfl_xor_sync(0xffffffffu, s, o);
    __shared__ float sm[8];
    if ((tid & 31) == 0) sm[tid >> 5] = s;
    __syncthreads();
    if (tid < 32) {
        float v = (tid < 8) ? sm[tid] : 0.f;
        #pragma unroll
        for (int o = 4; o > 0; o >>= 1) v += __shfl_xor_sync(0xffffffffu, v, o);
        if (tid == 0) dout[off + b] = v;
    }
}

// ---------------- 3x3 per-sample conv, COUT=8, NHWC, pad=1, relu ----------------
template<int CIN>
__global__ __launch_bounds__(256)
void conv3x3(const float* __restrict__ in, float* __restrict__ out,
             const float* __restrict__ flat, int woff, int boff, int H, int W)
{
    __shared__ __align__(16) float ws[CIN * 72];
    __shared__ float bs[8];
    __shared__ float tile[CIN][10][34];

    int b = blockIdx.z;
    const float* fb = flat + (size_t)b * OUTD;
    int tid = threadIdx.y * 32 + threadIdx.x;

    for (int idx = tid; idx < CIN * 72; idx += 256) {
        int o = idx & 7, it = idx >> 3;
        int i = it / 9, t = it - i * 9;
        ws[idx] = fb[woff + (o * CIN + i) * 9 + t];
    }
    if (tid < 8) bs[tid] = fb[boff + tid];

    int x0 = blockIdx.x * 32 - 1, y0 = blockIdx.y * 8 - 1;
    for (int idx = tid; idx < 340; idx += 256) {
        int yy = idx / 34, xx = idx - yy * 34;
        int gx = x0 + xx, gy = y0 + yy;
        bool inb = ((unsigned)gx < (unsigned)W) && ((unsigned)gy < (unsigned)H);
        if (inb) {
            const float* p = in + (((size_t)b * H + gy) * W + gx) * CIN;
            if (CIN == 2) {
                float2 q = *(const float2*)p;
                tile[0][yy][xx] = q.x;
                tile[1][yy][xx] = q.y;
            } else {
                #pragma unroll
                for (int c4 = 0; c4 < CIN; c4 += 4) {
                    float4 q = *(const float4*)(p + c4);
                    tile[c4 + 0][yy][xx] = q.x;
                    tile[c4 + 1][yy][xx] = q.y;
                    tile[c4 + 2][yy][xx] = q.z;
                    tile[c4 + 3][yy][xx] = q.w;
                }
            }
        } else {
            #pragma unroll
            for (int c = 0; c < CIN; c++) tile[c][yy][xx] = 0.f;
        }
    }
    __syncthreads();

    int tx = threadIdx.x, ty = threadIdx.y;
    u64 acc[4];
    #pragma unroll
    for (int p = 0; p < 4; p++) acc[p] = pack2(bs[2 * p], bs[2 * p + 1]);

    const u64* wsu = (const u64*)ws;
    #pragma unroll
    for (int i = 0; i < CIN; i++) {
        #pragma unroll
        for (int ky = 0; ky < 3; ky++)
            #pragma unroll
            for (int kx = 0; kx < 3; kx++) {
                u64 v = dup2f(tile[i][ty + ky][tx + kx]);
                int t = ky * 3 + kx;
                #pragma unroll
                for (int p = 0; p < 4; p++) ffma2(acc[p], v, wsu[(i * 9 + t) * 4 + p]);
            }
    }

    int gx = blockIdx.x * 32 + tx, gy = blockIdx.y * 8 + ty;
    if (gx >= W || gy >= H) return;
    float o_[8];
    #pragma unroll
    for (int p = 0; p < 4; p++) unpack2(acc[p], o_[2 * p], o_[2 * p + 1]);
    #pragma unroll
    for (int c = 0; c < 8; c++) o_[c] = fmaxf(o_[c], 0.f);
    float* po = out + (((size_t)b * H + gy) * W + gx) * 8;
    *(float4*)(po)     = make_float4(o_[0], o_[1], o_[2], o_[3]);
    *(float4*)(po + 4) = make_float4(o_[4], o_[5], o_[6], o_[7]);
}

// ---------------- 2x2 maxpool, NHWC C=8 ----------------
__device__ __forceinline__ float4 fmax4(float4 a, float4 b){
    return make_float4(fmaxf(a.x,b.x), fmaxf(a.y,b.y), fmaxf(a.z,b.z), fmaxf(a.w,b.w));
}
__global__ void maxpool2(const float* __restrict__ in, float* __restrict__ out, int Ho, int Wo)
{
    int idx = blockIdx.x * 256 + threadIdx.x;
    int total = NB * Ho * Wo;
    if (idx >= total) return;
    int x = idx % Wo; int r = idx / Wo; int y = r % Ho; int b = r / Ho;
    int Hi = 2 * Ho, Wi = 2 * Wo;
    const float4* p00 = (const float4*)(in + (((size_t)b * Hi + 2 * y) * Wi + 2 * x) * 8);
    const float4* p10 = (const float4*)(in + (((size_t)b * Hi + 2 * y + 1) * Wi + 2 * x) * 8);
    float4 a0 = fmax4(fmax4(p00[0], p00[2]), fmax4(p10[0], p10[2]));
    float4 a1 = fmax4(fmax4(p00[1], p00[3]), fmax4(p10[1], p10[3]));
    float* po = out + (((size_t)b * Ho + y) * Wo + x) * 8;
    *(float4*)(po)     = a0;
    *(float4*)(po + 4) = a1;
}

// ------- bilinear x2 (align_corners) upsample of sm (8ch) + concat skip (8ch) -------
__global__ void upcat(const float* __restrict__ sm, const float* __restrict__ skip,
                      float* __restrict__ out, int Hs, int Ws)
{
    int Ho = 2 * Hs, Wo = 2 * Ws;
    int idx = blockIdx.x * 256 + threadIdx.x;
    int total = NB * Ho * Wo;
    if (idx >= total) return;
    int x = idx % Wo; int r = idx / Wo; int y = r % Ho; int b = r / Ho;

    float fy = y * ((float)(Hs - 1) / (float)(Ho - 1));
    float fx = x * ((float)(Ws - 1) / (float)(Wo - 1));
    int y0 = (int)fy, x0 = (int)fx;
    int y1 = min(y0 + 1, Hs - 1), x1 = min(x0 + 1, Ws - 1);
    float ty = fy - (float)y0, tx = fx - (float)x0;
    float w00 = (1.f - ty) * (1.f - tx), w01 = (1.f - ty) * tx;
    float w10 = ty * (1.f - tx),         w11 = ty * tx;

    const float* p00 = sm + (((size_t)b * Hs + y0) * Ws + x0) * 8;
    const float* p01 = sm + (((size_t)b * Hs + y0) * Ws + x1) * 8;
    const float* p10 = sm + (((size_t)b * Hs + y1) * Ws + x0) * 8;
    const float* p11 = sm + (((size_t)b * Hs + y1) * Ws + x1) * 8;
    float* po = out + (((size_t)b * Ho + y) * Wo + x) * 16;
    #pragma unroll
    for (int c = 0; c < 8; c++)
        po[c] = w00 * p00[c] + w01 * p01[c] + w10 * p10[c] + w11 * p11[c];
    const float* ps = skip + (((size_t)b * Ho + y) * Wo + x) * 8;
    *(float4*)(po + 8)  = *(const float4*)ps;
    *(float4*)(po + 12) = *(const float4*)(ps + 4);
}

// ---------------- final 1x1 conv (8->2) + residual with zf ----------------
// w14 at flat offset 9360 (shape (2,8)), b14 at 9488.
__global__ void conv1x1_res(const float* __restrict__ in, const float* __restrict__ zf,
                            const float* __restrict__ flat, float* __restrict__ out)
{
    int idx = blockIdx.x * 256 + threadIdx.x;
    int total = NB * HWI * HWI;
    if (idx >= total) return;
    int b = idx / (HWI * HWI);
    const float* fb = flat + (size_t)b * OUTD;
    const float* p = in + (size_t)idx * 8;
    float4 a = *(const float4*)p, c = *(const float4*)(p + 4);
    float v[8] = {a.x, a.y, a.z, a.w, c.x, c.y, c.z, c.w};
    float o0 = fb[9488], o1 = fb[9489];          // b14
    #pragma unroll
    for (int i = 0; i < 8; i++) {
        o0 += fb[9360 + i]     * v[i];           // w14[0][i]
        o1 += fb[9360 + 8 + i] * v[i];           // w14[1][i]
    }
    float2 z = *(const float2*)(zf + (size_t)idx * 2);
    float2 r = make_float2(z.x + o0, z.y + o1);
    *(float2*)(out + (size_t)idx * 2) = r;
}

// ---------------- launcher ----------------
static float* sym(const void* s) {
    void* p = nullptr;
    cudaGetSymbolAddress(&p, s);
    return (float*)p;
}

extern "C" void kernel_launch(void* const* d_in, const int* in_sizes, int n_in,
                              void* d_out, int out_size)
{
    const float* zf  = (const float*)d_in[0];
    const float* hyp = (const float*)d_in[2];
    const float* hw1 = (const float*)d_in[3];  const float* hb1 = (const float*)d_in[4];
    const float* hw2 = (const float*)d_in[5];  const float* hb2 = (const float*)d_in[6];
    const float* hw3 = (const float*)d_in[7];  const float* hb3 = (const float*)d_in[8];
    const float* hw4 = (const float*)d_in[9];  const float* hb4 = (const float*)d_in[10];
    const float* hw5 = (const float*)d_in[11]; const float* hb5 = (const float*)d_in[12];
    const float* hwo = (const float*)d_in[13]; const float* hbo = (const float*)d_in[14];
    float* dout = (float*)d_out;

    float *h1 = sym(g_h1), *h2 = sym(g_h2), *ha = sym(g_ha), *hb = sym(g_hb), *fl = sym(g_flat);
    float *t0 = sym(g_t0), *c1 = sym(g_c1), *p1 = sym(g_p1), *t1 = sym(g_t1), *c2 = sym(g_c2);
    float *p2 = sym(g_p2), *t2 = sym(g_t2), *c3 = sym(g_c3), *p3 = sym(g_p3), *t3 = sym(g_t3);
    float *c4 = sym(g_c4), *u3 = sym(g_u3), *v3 = sym(g_v3), *w3 = sym(g_w3);
    float *u2 = sym(g_u2), *v2 = sym(g_v2), *w2 = sym(g_w2);
    float *u1 = sym(g_u1), *v1 = sym(g_v1), *w1 = sym(g_w1);

    // ---- hypernetwork ----
    fc_small<<<(NB * 100 + 255) / 256, 256>>>(hyp, hw1, hb1, h1, 1, 100);
    fc_small<<<(NB * 1000 + 255) / 256, 256>>>(h1, hw2, hb2, h2, 100, 1000);
    fc_big<<<(10000 + 15) / 16, 256>>>(h2, hw3, hb3, ha, 1000, 10000, 1);
    fc_big<<<(10000 + 15) / 16, 256>>>(ha, hw4, hb4, hb, 10000, 10000, 1);
    fc_big<<<(10000 + 15) / 16, 256>>>(hb, hw5, hb5, ha, 10000, 10000, 1);
    fc_big<<<(OUTD  + 15) / 16, 256>>>(ha, hwo, hbo, fl, 10000, OUTD, 0);
    l1norm<<<NB, 256>>>(fl, dout, NB * HWI * HWI * 2);

    // ---- U-Net ----
    // weight offsets: w0=0 w1=144 w2=720 w3=1296 w4=1872 w5=2448 w6=3024 w7=3600
    //                 w8=4176 w9=5328 w10=5904 w11=7056 w12=7632 w13=8784 w14=9360
    dim3 blk(32, 8);
    dim3 g256(8, 32, NB), g128(4, 16, NB), g64(2, 8, NB), g32(1, 4, NB);

    conv3x3<2><<<g256, blk>>>(zf, t0, fl, 0,    WBASE_B + 0,   256, 256);
    conv3x3<8><<<g256, blk>>>(t0, c1, fl, 144,  WBASE_B + 8,   256, 256);
    maxpool2<<<(NB * 128 * 128 + 255) / 256, 256>>>(c1, p1, 128, 128);
    conv3x3<8><<<g128, blk>>>(p1, t1, fl, 720,  WBASE_B + 16,  128, 128);
    conv3x3<8><<<g128, blk>>>(t1, c2, fl, 1296, WBASE_B + 24,  128, 128);
    maxpool2<<<(NB * 64 * 64 + 255) / 256, 256>>>(c2, p2, 64, 64);
    conv3x3<8><<<g64, blk>>>(p2, t2, fl, 1872,  WBASE_B + 32,  64, 64);
    conv3x3<8><<<g64, blk>>>(t2, c3, fl, 2448,  WBASE_B + 40,  64, 64);
    maxpool2<<<(NB * 32 * 32 + 255) / 256, 256>>>(c3, p3, 32, 32);
    conv3x3<8><<<g32, blk>>>(p3, t3, fl, 3024,  WBASE_B + 48,  32, 32);
    conv3x3<8><<<g32, blk>>>(t3, c4, fl, 3600,  WBASE_B + 56,  32, 32);

    upcat<<<(NB * 64 * 64 + 255) / 256, 256>>>(c4, c3, u3, 32, 32);
    conv3x3<16><<<g64, blk>>>(u3, v3, fl, 4176, WBASE_B + 64,  64, 64);
    conv3x3<8><<<g64, blk>>>(v3, w3, fl, 5328,  WBASE_B + 72,  64, 64);

    upcat<<<(NB * 128 * 128 + 255) / 256, 256>>>(w3, c2, u2, 64, 64);
    conv3x3<16><<<g128, blk>>>(u2, v2, fl, 5904, WBASE_B + 80, 128, 128);
    conv3x3<8><<<g128, blk>>>(v2, w2, fl, 7056,  WBASE_B + 88, 128, 128);

    upcat<<<(NB * 256 * 256 + 255) / 256, 256>>>(w2, c1, u1, 128, 128);
    conv3x3<16><<<g256, blk>>>(u1, v1, fl, 7632, WBASE_B + 96, 256, 256);
    conv3x3<8><<<g256, blk>>>(v1, w1, fl, 8784,  WBASE_B + 104, 256, 256);

    conv1x1_res<<<(NB * HWI * HWI + 255) / 256, 256>>>(w1, zf, fl, dout);
}

// round 9
// speedup vs baseline: 1.2377x; 1.0022x over previous
#include <cuda_runtime.h>
#include <math.h>

typedef unsigned long long u64;

#define NB   8
#define HWI  256
#define OUTD 9490
#define WBASE_B 9376   // bias region start in flat

// ---------------- packed f32x2 helpers ----------------
__device__ __forceinline__ u64 pack2(float lo, float hi){
    u64 r; asm("mov.b64 %0,{%1,%2};" : "=l"(r) : "f"(lo), "f"(hi)); return r;
}
__device__ __forceinline__ u64 dup2f(float v){
    u64 r; asm("mov.b64 %0,{%1,%1};" : "=l"(r) : "f"(v)); return r;
}
__device__ __forceinline__ void ffma2(u64 &d, u64 a, u64 b){
    asm("fma.rn.f32x2 %0,%1,%2,%3;" : "=l"(d) : "l"(a), "l"(b), "l"(d));
}
__device__ __forceinline__ void unpack2(u64 v, float &lo, float &hi){
    asm("mov.b64 {%0,%1},%2;" : "=f"(lo), "=f"(hi) : "l"(v));
}

// ---------------- static device scratch ----------------
__device__ __align__(16) float g_h1[NB*100];
__device__ __align__(16) float g_h2[NB*1000];
__device__ __align__(16) float g_ha[NB*10000];
__device__ __align__(16) float g_hb[NB*10000];
__device__ __align__(16) float g_flat[NB*OUTD];

__device__ __align__(16) float g_t0[NB*256*256*8];
__device__ __align__(16) float g_c1[NB*256*256*8];
__device__ __align__(16) float g_p1[NB*128*128*8];
__device__ __align__(16) float g_t1[NB*128*128*8];
__device__ __align__(16) float g_c2[NB*128*128*8];
__device__ __align__(16) float g_p2[NB*64*64*8];
__device__ __align__(16) float g_t2[NB*64*64*8];
__device__ __align__(16) float g_c3[NB*64*64*8];
__device__ __align__(16) float g_p3[NB*32*32*8];
__device__ __align__(16) float g_t3[NB*32*32*8];
__device__ __align__(16) float g_c4[NB*32*32*8];
__device__ __align__(16) float g_u3[NB*64*64*16];
__device__ __align__(16) float g_v3[NB*64*64*8];
__device__ __align__(16) float g_w3[NB*64*64*8];
__device__ __align__(16) float g_u2[NB*128*128*16];
__device__ __align__(16) float g_v2[NB*128*128*8];
__device__ __align__(16) float g_w2[NB*128*128*8];
__device__ __align__(16) float g_u1[NB*256*256*16];
__device__ __align__(16) float g_v1[NB*256*256*8];
__device__ __align__(16) float g_w1[NB*256*256*8];

// ---------------- small FC (layers 1, 2) ----------------
__global__ void fc_small(const float* __restrict__ in, const float* __restrict__ W,
                         const float* __restrict__ bias, float* __restrict__ out,
                         int K, int J)
{
    int t = blockIdx.x * blockDim.x + threadIdx.x;
    if (t >= NB * J) return;
    int b = t / J, j = t - b * J;
    const float* w = W + (size_t)j * K;
    const float* x = in + (size_t)b * K;
    float s = bias[j];
    for (int k = 0; k < K; k++) s += x[k] * w[k];
    out[t] = s > 0.f ? s : 0.01f * s;
}

// ---------------- big FC (layers 3,4,5,out) ----------------
// out[b][j] = act( sum_k in[b][k] * W[j][k] + bias[j] ), B = 8 fixed.
// Warp owns 2 rows. Lane l owns k = l*4 + 128*t (LDG.128 per row per t).
// Depth-2 register ring on W: iteration t computes with W(t) while W(t+2)
// is in flight. h double-buffered in smem: chunk c+1 staged during chunk c's
// compute. W prefetch indices are global-k, so the pipeline crosses chunk
// boundaries (registers survive the barrier).
#define FCB_CH 768           // k per chunk (6 compute iterations of 128)
#define FCB_IT (FCB_CH/128)
__global__ __launch_bounds__(256, 3)
void fc_big(const float* __restrict__ in, const float* __restrict__ W,
            const float* __restrict__ bias, float* __restrict__ out,
            int K, int J, int act)
{
    __shared__ __align__(16) float hs[2][8 * FCB_CH];   // 2 x 24 KB
    int tid  = threadIdx.x;
    int lane = tid & 31, warp = tid >> 5;
    int jbase = blockIdx.x * 16 + warp * 2;
    int j0 = min(jbase,     J - 1);
    int j1 = min(jbase + 1, J - 1);
    const float* W0 = W + (size_t)j0 * K;
    const float* W1 = W + (size_t)j1 * K;

    int nchunk = (K + FCB_CH - 1) / FCB_CH;
    int iters  = nchunk * FCB_IT;

    u64 acc[2][8];
    #pragma unroll
    for (int n = 0; n < 2; n++)
        #pragma unroll
        for (int b = 0; b < 8; b++) acc[n][b] = 0ULL;

    // ---- stage chunk 0 ----
    {
        int clen = min(FCB_CH, K);
        #pragma unroll
        for (int b = 0; b < 8; b++) {
            int r = (tid % 192) * 4;       // 192 float4 per batch row
            int bb = b;                     // 8*192 = 1536 float4, 256 thr -> 6 each
            // distribute: thread covers (b, r) pairs via flat index
        }
        for (int idx = tid; idx < 8 * (FCB_CH / 4); idx += 256) {
            int b = idx / (FCB_CH / 4), r = (idx - b * (FCB_CH / 4)) * 4;
            float4 v = (r < clen) ? *(const float4*)&in[b * K + r]
                                  : make_float4(0.f, 0.f, 0.f, 0.f);
            *(float4*)&hs[0][b * FCB_CH + r] = v;
        }
    }

    // ---- preload W ring (slots 0,1) ----
    ulonglong2 w0r[2], w1r[2];
    {
        int kg0 = min(lane * 4,        K - 4);
        int kg1 = min(128 + lane * 4,  K - 4);
        w0r[0] = __ldg((const ulonglong2*)(W0 + kg0));
        w1r[0] = __ldg((const ulonglong2*)(W1 + kg0));
        w0r[1] = __ldg((const ulonglong2*)(W0 + kg1));
        w1r[1] = __ldg((const ulonglong2*)(W1 + kg1));
    }
    __syncthreads();

    for (int c = 0; c < nchunk; c++) {
        const float* hb = hs[c & 1];
        // stage next chunk into the other buffer (overlaps with compute)
        if (c + 1 < nchunk) {
            int cb = (c + 1) * FCB_CH;
            int clen = min(FCB_CH, K - cb);
            for (int idx = tid; idx < 8 * (FCB_CH / 4); idx += 256) {
                int b = idx / (FCB_CH / 4), r = (idx - b * (FCB_CH / 4)) * 4;
                float4 v = (r < clen) ? *(const float4*)&in[b * K + cb + r]
                                      : make_float4(0.f, 0.f, 0.f, 0.f);
                *(float4*)&hs[(c + 1) & 1][b * FCB_CH + r] = v;
            }
        }
        #pragma unroll
        for (int tt = 0; tt < FCB_IT; tt++) {
            int t = c * FCB_IT + tt;
            int s = tt & 1;                     // == t&1 (FCB_IT even)
            ulonglong2 w0 = w0r[s], w1 = w1r[s];
            if (t + 2 < iters) {                // prefetch distance 2
                int kg = min((t + 2) * 128 + lane * 4, K - 4);
                w0r[s] = __ldg((const ulonglong2*)(W0 + kg));
                w1r[s] = __ldg((const ulonglong2*)(W1 + kg));
            }
            const float* hp = hb + tt * 128 + lane * 4;
            #pragma unroll
            for (int b = 0; b < 8; b++) {
                ulonglong2 h = *(const ulonglong2*)(hp + b * FCB_CH);
                ffma2(acc[0][b], w0.x, h.x);
                ffma2(acc[0][b], w0.y, h.y);
                ffma2(acc[1][b], w1.x, h.x);
                ffma2(acc[1][b], w1.y, h.y);
            }
        }
        __syncthreads();
    }

    float red[2][8];
    #pragma unroll
    for (int n = 0; n < 2; n++)
        #pragma unroll
        for (int b = 0; b < 8; b++) {
            float e, o;
            unpack2(acc[n][b], e, o);
            float s = e + o;
            #pragma unroll
            for (int sh = 16; sh > 0; sh >>= 1) s += __shfl_xor_sync(0xffffffffu, s, sh);
            red[n][b] = s;
        }
    if (lane == 0) {
        #pragma unroll
        for (int n = 0; n < 2; n++) {
            int j = jbase + n;
            if (j >= J) break;
            float bb = bias[j];
            #pragma unroll
            for (int b = 0; b < 8; b++) {
                float s = red[n][b] + bb;
                if (act) s = s > 0.f ? s : 0.01f * s;
                out[b * J + j] = s;
            }
        }
    }
}

// ---------------- L1 of generated params ----------------
__global__ void l1norm(const float* __restrict__ flat, float* __restrict__ dout, int off)
{
    int b = blockIdx.x, tid = threadIdx.x;
    float s = 0.f;
    for (int j = tid; j < OUTD; j += 256) s += fabsf(flat[b * OUTD + j]);
    #pragma unroll
    for (int o = 16; o > 0; o >>= 1) s += __shfl_xor_sync(0xffffffffu, s, o);
    __shared__ float sm[8];
    if ((tid & 31) == 0) sm[tid >> 5] = s;
    __syncthreads();
    if (tid < 32) {
        float v = (tid < 8) ? sm[tid] : 0.f;
        #pragma unroll
        for (int o = 4; o > 0; o >>= 1) v += __shfl_xor_sync(0xffffffffu, v, o);
        if (tid == 0) dout[off + b] = v;
    }
}

// ---------------- 3x3 per-sample conv, COUT=8, NHWC, pad=1, relu ----------------
template<int CIN>
__global__ __launch_bounds__(256)
void conv3x3(const float* __restrict__ in, float* __restrict__ out,
             const float* __restrict__ flat, int woff, int boff, int H, int W)
{
    __shared__ __align__(16) float ws[CIN * 72];
    __shared__ float bs[8];
    __shared__ float tile[CIN][10][34];

    int b = blockIdx.z;
    const float* fb = flat + (size_t)b * OUTD;
    int tid = threadIdx.y * 32 + threadIdx.x;

    for (int idx = tid; idx < CIN * 72; idx += 256) {
        int o = idx & 7, it = idx >> 3;
        int i = it / 9, t = it - i * 9;
        ws[idx] = fb[woff + (o * CIN + i) * 9 + t];
    }
    if (tid < 8) bs[tid] = fb[boff + tid];

    int x0 = blockIdx.x * 32 - 1, y0 = blockIdx.y * 8 - 1;
    for (int idx = tid; idx < 340; idx += 256) {
        int yy = idx / 34, xx = idx - yy * 34;
        int gx = x0 + xx, gy = y0 + yy;
        bool inb = ((unsigned)gx < (unsigned)W) && ((unsigned)gy < (unsigned)H);
        if (inb) {
            const float* p = in + (((size_t)b * H + gy) * W + gx) * CIN;
            if (CIN == 2) {
                float2 q = *(const float2*)p;
                tile[0][yy][xx] = q.x;
                tile[1][yy][xx] = q.y;
            } else {
                #pragma unroll
                for (int c4 = 0; c4 < CIN; c4 += 4) {
                    float4 q = *(const float4*)(p + c4);
                    tile[c4 + 0][yy][xx] = q.x;
                    tile[c4 + 1][yy][xx] = q.y;
                    tile[c4 + 2][yy][xx] = q.z;
                    tile[c4 + 3][yy][xx] = q.w;
                }
            }
        } else {
            #pragma unroll
            for (int c = 0; c < CIN; c++) tile[c][yy][xx] = 0.f;
        }
    }
    __syncthreads();

    int tx = threadIdx.x, ty = threadIdx.y;
    u64 acc[4];
    #pragma unroll
    for (int p = 0; p < 4; p++) acc[p] = pack2(bs[2 * p], bs[2 * p + 1]);

    const u64* wsu = (const u64*)ws;
    #pragma unroll
    for (int i = 0; i < CIN; i++) {
        #pragma unroll
        for (int ky = 0; ky < 3; ky++)
            #pragma unroll
            for (int kx = 0; kx < 3; kx++) {
                u64 v = dup2f(tile[i][ty + ky][tx + kx]);
                int t = ky * 3 + kx;
                #pragma unroll
                for (int p = 0; p < 4; p++) ffma2(acc[p], v, wsu[(i * 9 + t) * 4 + p]);
            }
    }

    int gx = blockIdx.x * 32 + tx, gy = blockIdx.y * 8 + ty;
    if (gx >= W || gy >= H) return;
    float o_[8];
    #pragma unroll
    for (int p = 0; p < 4; p++) unpack2(acc[p], o_[2 * p], o_[2 * p + 1]);
    #pragma unroll
    for (int c = 0; c < 8; c++) o_[c] = fmaxf(o_[c], 0.f);
    float* po = out + (((size_t)b * H + gy) * W + gx) * 8;
    *(float4*)(po)     = make_float4(o_[0], o_[1], o_[2], o_[3]);
    *(float4*)(po + 4) = make_float4(o_[4], o_[5], o_[6], o_[7]);
}

// ---------------- 2x2 maxpool, NHWC C=8 ----------------
__device__ __forceinline__ float4 fmax4(float4 a, float4 b){
    return make_float4(fmaxf(a.x,b.x), fmaxf(a.y,b.y), fmaxf(a.z,b.z), fmaxf(a.w,b.w));
}
__global__ void maxpool2(const float* __restrict__ in, float* __restrict__ out, int Ho, int Wo)
{
    int idx = blockIdx.x * 256 + threadIdx.x;
    int total = NB * Ho * Wo;
    if (idx >= total) return;
    int x = idx % Wo; int r = idx / Wo; int y = r % Ho; int b = r / Ho;
    int Hi = 2 * Ho, Wi = 2 * Wo;
    const float4* p00 = (const float4*)(in + (((size_t)b * Hi + 2 * y) * Wi + 2 * x) * 8);
    const float4* p10 = (const float4*)(in + (((size_t)b * Hi + 2 * y + 1) * Wi + 2 * x) * 8);
    float4 a0 = fmax4(fmax4(p00[0], p00[2]), fmax4(p10[0], p10[2]));
    float4 a1 = fmax4(fmax4(p00[1], p00[3]), fmax4(p10[1], p10[3]));
    float* po = out + (((size_t)b * Ho + y) * Wo + x) * 8;
    *(float4*)(po)     = a0;
    *(float4*)(po + 4) = a1;
}

// ------- bilinear x2 (align_corners) upsample of sm (8ch) + concat skip (8ch) -------
__global__ void upcat(const float* __restrict__ sm, const float* __restrict__ skip,
                      float* __restrict__ out, int Hs, int Ws)
{
    int Ho = 2 * Hs, Wo = 2 * Ws;
    int idx = blockIdx.x * 256 + threadIdx.x;
    int total = NB * Ho * Wo;
    if (idx >= total) return;
    int x = idx % Wo; int r = idx / Wo; int y = r % Ho; int b = r / Ho;

    float fy = y * ((float)(Hs - 1) / (float)(Ho - 1));
    float fx = x * ((float)(Ws - 1) / (float)(Wo - 1));
    int y0 = (int)fy, x0 = (int)fx;
    int y1 = min(y0 + 1, Hs - 1), x1 = min(x0 + 1, Ws - 1);
    float ty = fy - (float)y0, tx = fx - (float)x0;
    float w00 = (1.f - ty) * (1.f - tx), w01 = (1.f - ty) * tx;
    float w10 = ty * (1.f - tx),         w11 = ty * tx;

    const float* p00 = sm + (((size_t)b * Hs + y0) * Ws + x0) * 8;
    const float* p01 = sm + (((size_t)b * Hs + y0) * Ws + x1) * 8;
    const float* p10 = sm + (((size_t)b * Hs + y1) * Ws + x0) * 8;
    const float* p11 = sm + (((size_t)b * Hs + y1) * Ws + x1) * 8;
    float* po = out + (((size_t)b * Ho + y) * Wo + x) * 16;
    #pragma unroll
    for (int c = 0; c < 8; c++)
        po[c] = w00 * p00[c] + w01 * p01[c] + w10 * p10[c] + w11 * p11[c];
    const float* ps = skip + (((size_t)b * Ho + y) * Wo + x) * 8;
    *(float4*)(po + 8)  = *(const float4*)ps;
    *(float4*)(po + 12) = *(const float4*)(ps + 4);
}

// ---------------- final 1x1 conv (8->2) + residual with zf ----------------
// w14 at flat offset 9360 (shape (2,8)), b14 at 9488.
__global__ void conv1x1_res(const float* __restrict__ in, const float* __restrict__ zf,
                            const float* __restrict__ flat, float* __restrict__ out)
{
    int idx = blockIdx.x * 256 + threadIdx.x;
    int total = NB * HWI * HWI;
    if (idx >= total) return;
    int b = idx / (HWI * HWI);
    const float* fb = flat + (size_t)b * OUTD;
    const float* p = in + (size_t)idx * 8;
    float4 a = *(const float4*)p, c = *(const float4*)(p + 4);
    float v[8] = {a.x, a.y, a.z, a.w, c.x, c.y, c.z, c.w};
    float o0 = fb[9488], o1 = fb[9489];          // b14
    #pragma unroll
    for (int i = 0; i < 8; i++) {
        o0 += fb[9360 + i]     * v[i];           // w14[0][i]
        o1 += fb[9360 + 8 + i] * v[i];           // w14[1][i]
    }
    float2 z = *(const float2*)(zf + (size_t)idx * 2);
    float2 r = make_float2(z.x + o0, z.y + o1);
    *(float2*)(out + (size_t)idx * 2) = r;
}

// ---------------- launcher ----------------
static float* sym(const void* s) {
    void* p = nullptr;
    cudaGetSymbolAddress(&p, s);
    return (float*)p;
}

extern "C" void kernel_launch(void* const* d_in, const int* in_sizes, int n_in,
                              void* d_out, int out_size)
{
    const float* zf  = (const float*)d_in[0];
    const float* hyp = (const float*)d_in[2];
    const float* hw1 = (const float*)d_in[3];  const float* hb1 = (const float*)d_in[4];
    const float* hw2 = (const float*)d_in[5];  const float* hb2 = (const float*)d_in[6];
    const float* hw3 = (const float*)d_in[7];  const float* hb3 = (const float*)d_in[8];
    const float* hw4 = (const float*)d_in[9];  const float* hb4 = (const float*)d_in[10];
    const float* hw5 = (const float*)d_in[11]; const float* hb5 = (const float*)d_in[12];
    const float* hwo = (const float*)d_in[13]; const float* hbo = (const float*)d_in[14];
    float* dout = (float*)d_out;

    float *h1 = sym(g_h1), *h2 = sym(g_h2), *ha = sym(g_ha), *hb = sym(g_hb), *fl = sym(g_flat);
    float *t0 = sym(g_t0), *c1 = sym(g_c1), *p1 = sym(g_p1), *t1 = sym(g_t1), *c2 = sym(g_c2);
    float *p2 = sym(g_p2), *t2 = sym(g_t2), *c3 = sym(g_c3), *p3 = sym(g_p3), *t3 = sym(g_t3);
    float *c4 = sym(g_c4), *u3 = sym(g_u3), *v3 = sym(g_v3), *w3 = sym(g_w3);
    float *u2 = sym(g_u2), *v2 = sym(g_v2), *w2 = sym(g_w2);
    float *u1 = sym(g_u1), *v1 = sym(g_v1), *w1 = sym(g_w1);

    // ---- hypernetwork ----
    fc_small<<<(NB * 100 + 255) / 256, 256>>>(hyp, hw1, hb1, h1, 1, 100);
    fc_small<<<(NB * 1000 + 255) / 256, 256>>>(h1, hw2, hb2, h2, 100, 1000);
    fc_big<<<(10000 + 15) / 16, 256>>>(h2, hw3, hb3, ha, 1000, 10000, 1);
    fc_big<<<(10000 + 15) / 16, 256>>>(ha, hw4, hb4, hb, 10000, 10000, 1);
    fc_big<<<(10000 + 15) / 16, 256>>>(hb, hw5, hb5, ha, 10000, 10000, 1);
    fc_big<<<(OUTD  + 15) / 16, 256>>>(ha, hwo, hbo, fl, 10000, OUTD, 0);
    l1norm<<<NB, 256>>>(fl, dout, NB * HWI * HWI * 2);

    // ---- U-Net ----
    // weight offsets: w0=0 w1=144 w2=720 w3=1296 w4=1872 w5=2448 w6=3024 w7=3600
    //                 w8=4176 w9=5328 w10=5904 w11=7056 w12=7632 w13=8784 w14=9360
    dim3 blk(32, 8);
    dim3 g256(8, 32, NB), g128(4, 16, NB), g64(2, 8, NB), g32(1, 4, NB);

    conv3x3<2><<<g256, blk>>>(zf, t0, fl, 0,    WBASE_B + 0,   256, 256);
    conv3x3<8><<<g256, blk>>>(t0, c1, fl, 144,  WBASE_B + 8,   256, 256);
    maxpool2<<<(NB * 128 * 128 + 255) / 256, 256>>>(c1, p1, 128, 128);
    conv3x3<8><<<g128, blk>>>(p1, t1, fl, 720,  WBASE_B + 16,  128, 128);
    conv3x3<8><<<g128, blk>>>(t1, c2, fl, 1296, WBASE_B + 24,  128, 128);
    maxpool2<<<(NB * 64 * 64 + 255) / 256, 256>>>(c2, p2, 64, 64);
    conv3x3<8><<<g64, blk>>>(p2, t2, fl, 1872,  WBASE_B + 32,  64, 64);
    conv3x3<8><<<g64, blk>>>(t2, c3, fl, 2448,  WBASE_B + 40,  64, 64);
    maxpool2<<<(NB * 32 * 32 + 255) / 256, 256>>>(c3, p3, 32, 32);
    conv3x3<8><<<g32, blk>>>(p3, t3, fl, 3024,  WBASE_B + 48,  32, 32);
    conv3x3<8><<<g32, blk>>>(t3, c4, fl, 3600,  WBASE_B + 56,  32, 32);

    upcat<<<(NB * 64 * 64 + 255) / 256, 256>>>(c4, c3, u3, 32, 32);
    conv3x3<16><<<g64, blk>>>(u3, v3, fl, 4176, WBASE_B + 64,  64, 64);
    conv3x3<8><<<g64, blk>>>(v3, w3, fl, 5328,  WBASE_B + 72,  64, 64);

    upcat<<<(NB * 128 * 128 + 255) / 256, 256>>>(w3, c2, u2, 64, 64);
    conv3x3<16><<<g128, blk>>>(u2, v2, fl, 5904, WBASE_B + 80, 128, 128);
    conv3x3<8><<<g128, blk>>>(v2, w2, fl, 7056,  WBASE_B + 88, 128, 128);

    upcat<<<(NB * 256 * 256 + 255) / 256, 256>>>(w2, c1, u1, 128, 128);
    conv3x3<16><<<g256, blk>>>(u1, v1, fl, 7632, WBASE_B + 96, 256, 256);
    conv3x3<8><<<g256, blk>>>(v1, w1, fl, 8784,  WBASE_B + 104, 256, 256);

    conv1x1_res<<<(NB * HWI * HWI + 255) / 256, 256>>>(w1, zf, fl, dout);
}

// round 10
// speedup vs baseline: 1.2383x; 1.0005x over previous
#include <cuda_runtime.h>
#include <math.h>

typedef unsigned long long u64;

#define NB   8
#define HWI  256
#define OUTD 9490
#define WBASE_B 9376   // bias region start in flat

// ---------------- packed f32x2 helpers ----------------
__device__ __forceinline__ u64 pack2(float lo, float hi){
    u64 r; asm("mov.b64 %0,{%1,%2};" : "=l"(r) : "f"(lo), "f"(hi)); return r;
}
__device__ __forceinline__ u64 dup2f(float v){
    u64 r; asm("mov.b64 %0,{%1,%1};" : "=l"(r) : "f"(v)); return r;
}
__device__ __forceinline__ void ffma2(u64 &d, u64 a, u64 b){
    asm("fma.rn.f32x2 %0,%1,%2,%3;" : "=l"(d) : "l"(a), "l"(b), "l"(d));
}
__device__ __forceinline__ void unpack2(u64 v, float &lo, float &hi){
    asm("mov.b64 {%0,%1},%2;" : "=f"(lo), "=f"(hi) : "l"(v));
}

// ---------------- static device scratch ----------------
__device__ __align__(16) float g_h1[NB*100];
__device__ __align__(16) float g_h2[NB*1000];
__device__ __align__(16) float g_ha[NB*10000];
__device__ __align__(16) float g_hb[NB*10000];
__device__ __align__(16) float g_flat[NB*OUTD];

__device__ __align__(16) float g_t0[NB*256*256*8];
__device__ __align__(16) float g_c1[NB*256*256*8];
__device__ __align__(16) float g_p1[NB*128*128*8];
__device__ __align__(16) float g_t1[NB*128*128*8];
__device__ __align__(16) float g_c2[NB*128*128*8];
__device__ __align__(16) float g_p2[NB*64*64*8];
__device__ __align__(16) float g_t2[NB*64*64*8];
__device__ __align__(16) float g_c3[NB*64*64*8];
__device__ __align__(16) float g_p3[NB*32*32*8];
__device__ __align__(16) float g_t3[NB*32*32*8];
__device__ __align__(16) float g_c4[NB*32*32*8];
__device__ __align__(16) float g_u3[NB*64*64*16];
__device__ __align__(16) float g_v3[NB*64*64*8];
__device__ __align__(16) float g_w3[NB*64*64*8];
__device__ __align__(16) float g_u2[NB*128*128*16];
__device__ __align__(16) float g_v2[NB*128*128*8];
__device__ __align__(16) float g_w2[NB*128*128*8];
__device__ __align__(16) float g_u1[NB*256*256*16];
__device__ __align__(16) float g_v1[NB*256*256*8];
__device__ __align__(16) float g_w1[NB*256*256*8];

// ---------------- small FC (layers 1, 2) ----------------
__global__ void fc_small(const float* __restrict__ in, const float* __restrict__ W,
                         const float* __restrict__ bias, float* __restrict__ out,
                         int K, int J)
{
    int t = blockIdx.x * blockDim.x + threadIdx.x;
    if (t >= NB * J) return;
    int b = t / J, j = t - b * J;
    const float* w = W + (size_t)j * K;
    const float* x = in + (size_t)b * K;
    float s = bias[j];
    for (int k = 0; k < K; k++) s += x[k] * w[k];
    out[t] = s > 0.f ? s : 0.01f * s;
}

// ---------------- big FC (layers 3,4,5,out) ----------------
// out[b][j] = act( sum_k in[b][k] * W[j][k] + bias[j] ), B = 8 fixed.
// Warp owns 2 rows. Lane l owns k = l*4 + 128*t (LDG.128 per row per t).
// Depth-2 register ring on W: iteration t computes with W(t) while W(t+2)
// is in flight. h double-buffered in smem: chunk c+1 staged during chunk c's
// compute. W prefetch indices are global-k, so the pipeline crosses chunk
// boundaries (registers survive the barrier).
#define FCB_CH 768           // k per chunk (6 compute iterations of 128)
#define FCB_IT (FCB_CH/128)
__global__ __launch_bounds__(256, 3)
void fc_big(const float* __restrict__ in, const float* __restrict__ W,
            const float* __restrict__ bias, float* __restrict__ out,
            int K, int J, int act)
{
    __shared__ __align__(16) float hs[2][8 * FCB_CH];   // 2 x 24 KB
    int tid  = threadIdx.x;
    int lane = tid & 31, warp = tid >> 5;
    int jbase = blockIdx.x * 16 + warp * 2;
    int j0 = min(jbase,     J - 1);
    int j1 = min(jbase + 1, J - 1);
    const float* W0 = W + (size_t)j0 * K;
    const float* W1 = W + (size_t)j1 * K;

    int nchunk = (K + FCB_CH - 1) / FCB_CH;
    int iters  = nchunk * FCB_IT;

    u64 acc[2][8];
    #pragma unroll
    for (int n = 0; n < 2; n++)
        #pragma unroll
        for (int b = 0; b < 8; b++) acc[n][b] = 0ULL;

    // ---- stage chunk 0 ----
    {
        int clen = min(FCB_CH, K);
        #pragma unroll
        for (int b = 0; b < 8; b++) {
            int r = (tid % 192) * 4;       // 192 float4 per batch row
            int bb = b;                     // 8*192 = 1536 float4, 256 thr -> 6 each
            // distribute: thread covers (b, r) pairs via flat index
        }
        for (int idx = tid; idx < 8 * (FCB_CH / 4); idx += 256) {
            int b = idx / (FCB_CH / 4), r = (idx - b * (FCB_CH / 4)) * 4;
            float4 v = (r < clen) ? *(const float4*)&in[b * K + r]
                                  : make_float4(0.f, 0.f, 0.f, 0.f);
            *(float4*)&hs[0][b * FCB_CH + r] = v;
        }
    }

    // ---- preload W ring (slots 0,1) ----
    ulonglong2 w0r[2], w1r[2];
    {
        int kg0 = min(lane * 4,        K - 4);
        int kg1 = min(128 + lane * 4,  K - 4);
        w0r[0] = __ldg((const ulonglong2*)(W0 + kg0));
        w1r[0] = __ldg((const ulonglong2*)(W1 + kg0));
        w0r[1] = __ldg((const ulonglong2*)(W0 + kg1));
        w1r[1] = __ldg((const ulonglong2*)(W1 + kg1));
    }
    __syncthreads();

    for (int c = 0; c < nchunk; c++) {
        const float* hb = hs[c & 1];
        // stage next chunk into the other buffer (overlaps with compute)
        if (c + 1 < nchunk) {
            int cb = (c + 1) * FCB_CH;
            int clen = min(FCB_CH, K - cb);
            for (int idx = tid; idx < 8 * (FCB_CH / 4); idx += 256) {
                int b = idx / (FCB_CH / 4), r = (idx - b * (FCB_CH / 4)) * 4;
                float4 v = (r < clen) ? *(const float4*)&in[b * K + cb + r]
                                      : make_float4(0.f, 0.f, 0.f, 0.f);
                *(float4*)&hs[(c + 1) & 1][b * FCB_CH + r] = v;
            }
        }
        #pragma unroll
        for (int tt = 0; tt < FCB_IT; tt++) {
            int t = c * FCB_IT + tt;
            int s = tt & 1;                     // == t&1 (FCB_IT even)
            ulonglong2 w0 = w0r[s], w1 = w1r[s];
            if (t + 2 < iters) {                // prefetch distance 2
                int kg = min((t + 2) * 128 + lane * 4, K - 4);
                w0r[s] = __ldg((const ulonglong2*)(W0 + kg));
                w1r[s] = __ldg((const ulonglong2*)(W1 + kg));
            }
            const float* hp = hb + tt * 128 + lane * 4;
            #pragma unroll
            for (int b = 0; b < 8; b++) {
                ulonglong2 h = *(const ulonglong2*)(hp + b * FCB_CH);
                ffma2(acc[0][b], w0.x, h.x);
                ffma2(acc[0][b], w0.y, h.y);
                ffma2(acc[1][b], w1.x, h.x);
                ffma2(acc[1][b], w1.y, h.y);
            }
        }
        __syncthreads();
    }

    float red[2][8];
    #pragma unroll
    for (int n = 0; n < 2; n++)
        #pragma unroll
        for (int b = 0; b < 8; b++) {
            float e, o;
            unpack2(acc[n][b], e, o);
            float s = e + o;
            #pragma unroll
            for (int sh = 16; sh > 0; sh >>= 1) s += __shfl_xor_sync(0xffffffffu, s, sh);
            red[n][b] = s;
        }
    if (lane == 0) {
        #pragma unroll
        for (int n = 0; n < 2; n++) {
            int j = jbase + n;
            if (j >= J) break;
            float bb = bias[j];
            #pragma unroll
            for (int b = 0; b < 8; b++) {
                float s = red[n][b] + bb;
                if (act) s = s > 0.f ? s : 0.01f * s;
                out[b * J + j] = s;
            }
        }
    }
}

// ---------------- L1 of generated params ----------------
__global__ void l1norm(const float* __restrict__ flat, float* __restrict__ dout, int off)
{
    int b = blockIdx.x, tid = threadIdx.x;
    float s = 0.f;
    for (int j = tid; j < OUTD; j += 256) s += fabsf(flat[b * OUTD + j]);
    #pragma unroll
    for (int o = 16; o > 0; o >>= 1) s += __shfl_xor_sync(0xffffffffu, s, o);
    __shared__ float sm[8];
    if ((tid & 31) == 0) sm[tid >> 5] = s;
    __syncthreads();
    if (tid < 32) {
        float v = (tid < 8) ? sm[tid] : 0.f;
        #pragma unroll
        for (int o = 4; o > 0; o >>= 1) v += __shfl_xor_sync(0xffffffffu, v, o);
        if (tid == 0) dout[off + b] = v;
    }
}

// ---------------- 3x3 per-sample conv, COUT=8, NHWC, pad=1, relu ----------------
template<int CIN>
__global__ __launch_bounds__(256)
void conv3x3(const float* __restrict__ in, float* __restrict__ out,
             const float* __restrict__ flat, int woff, int boff, int H, int W)
{
    __shared__ __align__(16) float ws[CIN * 72];
    __shared__ float bs[8];
    __shared__ float tile[CIN][10][34];

    int b = blockIdx.z;
    const float* fb = flat + (size_t)b * OUTD;
    int tid = threadIdx.y * 32 + threadIdx.x;

    for (int idx = tid; idx < CIN * 72; idx += 256) {
        int o = idx & 7, it = idx >> 3;
        int i = it / 9, t = it - i * 9;
        ws[idx] = fb[woff + (o * CIN + i) * 9 + t];
    }
    if (tid < 8) bs[tid] = fb[boff + tid];

    int x0 = blockIdx.x * 32 - 1, y0 = blockIdx.y * 8 - 1;
    for (int idx = tid; idx < 340; idx += 256) {
        int yy = idx / 34, xx = idx - yy * 34;
        int gx = x0 + xx, gy = y0 + yy;
        bool inb = ((unsigned)gx < (unsigned)W) && ((unsigned)gy < (unsigned)H);
        if (inb) {
            const float* p = in + (((size_t)b * H + gy) * W + gx) * CIN;
            if (CIN == 2) {
                float2 q = *(const float2*)p;
                tile[0][yy][xx] = q.x;
                tile[1][yy][xx] = q.y;
            } else {
                #pragma unroll
                for (int c4 = 0; c4 < CIN; c4 += 4) {
                    float4 q = *(const float4*)(p + c4);
                    tile[c4 + 0][yy][xx] = q.x;
                    tile[c4 + 1][yy][xx] = q.y;
                    tile[c4 + 2][yy][xx] = q.z;
                    tile[c4 + 3][yy][xx] = q.w;
                }
            }
        } else {
            #pragma unroll
            for (int c = 0; c < CIN; c++) tile[c][yy][xx] = 0.f;
        }
    }
    __syncthreads();

    int tx = threadIdx.x, ty = threadIdx.y;
    u64 acc[4];
    #pragma unroll
    for (int p = 0; p < 4; p++) acc[p] = pack2(bs[2 * p], bs[2 * p + 1]);

    const u64* wsu = (const u64*)ws;
    #pragma unroll
    for (int i = 0; i < CIN; i++) {
        #pragma unroll
        for (int ky = 0; ky < 3; ky++)
            #pragma unroll
            for (int kx = 0; kx < 3; kx++) {
                u64 v = dup2f(tile[i][ty + ky][tx + kx]);
                int t = ky * 3 + kx;
                #pragma unroll
                for (int p = 0; p < 4; p++) ffma2(acc[p], v, wsu[(i * 9 + t) * 4 + p]);
            }
    }

    int gx = blockIdx.x * 32 + tx, gy = blockIdx.y * 8 + ty;
    if (gx >= W || gy >= H) return;
    float o_[8];
    #pragma unroll
    for (int p = 0; p < 4; p++) unpack2(acc[p], o_[2 * p], o_[2 * p + 1]);
    #pragma unroll
    for (int c = 0; c < 8; c++) o_[c] = fmaxf(o_[c], 0.f);
    float* po = out + (((size_t)b * H + gy) * W + gx) * 8;
    *(float4*)(po)     = make_float4(o_[0], o_[1], o_[2], o_[3]);
    *(float4*)(po + 4) = make_float4(o_[4], o_[5], o_[6], o_[7]);
}

// ---------------- 2x2 maxpool, NHWC C=8 ----------------
__device__ __forceinline__ float4 fmax4(float4 a, float4 b){
    return make_float4(fmaxf(a.x,b.x), fmaxf(a.y,b.y), fmaxf(a.z,b.z), fmaxf(a.w,b.w));
}
__global__ void maxpool2(const float* __restrict__ in, float* __restrict__ out, int Ho, int Wo)
{
    int idx = blockIdx.x * 256 + threadIdx.x;
    int total = NB * Ho * Wo;
    if (idx >= total) return;
    int x = idx % Wo; int r = idx / Wo; int y = r % Ho; int b = r / Ho;
    int Hi = 2 * Ho, Wi = 2 * Wo;
    const float4* p00 = (const float4*)(in + (((size_t)b * Hi + 2 * y) * Wi + 2 * x) * 8);
    const float4* p10 = (const float4*)(in + (((size_t)b * Hi + 2 * y + 1) * Wi + 2 * x) * 8);
    float4 a0 = fmax4(fmax4(p00[0], p00[2]), fmax4(p10[0], p10[2]));
    float4 a1 = fmax4(fmax4(p00[1], p00[3]), fmax4(p10[1], p10[3]));
    float* po = out + (((size_t)b * Ho + y) * Wo + x) * 8;
    *(float4*)(po)     = a0;
    *(float4*)(po + 4) = a1;
}

// ------- bilinear x2 (align_corners) upsample of sm (8ch) + concat skip (8ch) -------
__global__ void upcat(const float* __restrict__ sm, const float* __restrict__ skip,
                      float* __restrict__ out, int Hs, int Ws)
{
    int Ho = 2 * Hs, Wo = 2 * Ws;
    int idx = blockIdx.x * 256 + threadIdx.x;
    int total = NB * Ho * Wo;
    if (idx >= total) return;
    int x = idx % Wo; int r = idx / Wo; int y = r % Ho; int b = r / Ho;

    float fy = y * ((float)(Hs - 1) / (float)(Ho - 1));
    float fx = x * ((float)(Ws - 1) / (float)(Wo - 1));
    int y0 = (int)fy, x0 = (int)fx;
    int y1 = min(y0 + 1, Hs - 1), x1 = min(x0 + 1, Ws - 1);
    float ty = fy - (float)y0, tx = fx - (float)x0;
    float w00 = (1.f - ty) * (1.f - tx), w01 = (1.f - ty) * tx;
    float w10 = ty * (1.f - tx),         w11 = ty * tx;

    const float* p00 = sm + (((size_t)b * Hs + y0) * Ws + x0) * 8;
    const float* p01 = sm + (((size_t)b * Hs + y0) * Ws + x1) * 8;
    const float* p10 = sm + (((size_t)b * Hs + y1) * Ws + x0) * 8;
    const float* p11 = sm + (((size_t)b * Hs + y1) * Ws + x1) * 8;
    float* po = out + (((size_t)b * Ho + y) * Wo + x) * 16;
    #pragma unroll
    for (int c = 0; c < 8; c++)
        po[c] = w00 * p00[c] + w01 * p01[c] + w10 * p10[c] + w11 * p11[c];
    const float* ps = skip + (((size_t)b * Ho + y) * Wo + x) * 8;
    *(float4*)(po + 8)  = *(const float4*)ps;
    *(float4*)(po + 12) = *(const float4*)(ps + 4);
}

// ---------------- final 1x1 conv (8->2) + residual with zf ----------------
// w14 at flat offset 9360 (shape (2,8)), b14 at 9488.
__global__ void conv1x1_res(const float* __restrict__ in, const float* __restrict__ zf,
                            const float* __restrict__ flat, float* __restrict__ out)
{
    int idx = blockIdx.x * 256 + threadIdx.x;
    int total = NB * HWI * HWI;
    if (idx >= total) return;
    int b = idx / (HWI * HWI);
    const float* fb = flat + (size_t)b * OUTD;
    const float* p = in + (size_t)idx * 8;
    float4 a = *(const float4*)p, c = *(const float4*)(p + 4);
    float v[8] = {a.x, a.y, a.z, a.w, c.x, c.y, c.z, c.w};
    float o0 = fb[9488], o1 = fb[9489];          // b14
    #pragma unroll
    for (int i = 0; i < 8; i++) {
        o0 += fb[9360 + i]     * v[i];           // w14[0][i]
        o1 += fb[9360 + 8 + i] * v[i];           // w14[1][i]
    }
    float2 z = *(const float2*)(zf + (size_t)idx * 2);
    float2 r = make_float2(z.x + o0, z.y + o1);
    *(float2*)(out + (size_t)idx * 2) = r;
}

// ---------------- launcher ----------------
static float* sym(const void* s) {
    void* p = nullptr;
    cudaGetSymbolAddress(&p, s);
    return (float*)p;
}

extern "C" void kernel_launch(void* const* d_in, const int* in_sizes, int n_in,
                              void* d_out, int out_size)
{
    const float* zf  = (const float*)d_in[0];
    const float* hyp = (const float*)d_in[2];
    const float* hw1 = (const float*)d_in[3];  const float* hb1 = (const float*)d_in[4];
    const float* hw2 = (const float*)d_in[5];  const float* hb2 = (const float*)d_in[6];
    const float* hw3 = (const float*)d_in[7];  const float* hb3 = (const float*)d_in[8];
    const float* hw4 = (const float*)d_in[9];  const float* hb4 = (const float*)d_in[10];
    const float* hw5 = (const float*)d_in[11]; const float* hb5 = (const float*)d_in[12];
    const float* hwo = (const float*)d_in[13]; const float* hbo = (const float*)d_in[14];
    float* dout = (float*)d_out;

    float *h1 = sym(g_h1), *h2 = sym(g_h2), *ha = sym(g_ha), *hb = sym(g_hb), *fl = sym(g_flat);
    float *t0 = sym(g_t0), *c1 = sym(g_c1), *p1 = sym(g_p1), *t1 = sym(g_t1), *c2 = sym(g_c2);
    float *p2 = sym(g_p2), *t2 = sym(g_t2), *c3 = sym(g_c3), *p3 = sym(g_p3), *t3 = sym(g_t3);
    float *c4 = sym(g_c4), *u3 = sym(g_u3), *v3 = sym(g_v3), *w3 = sym(g_w3);
    float *u2 = sym(g_u2), *v2 = sym(g_v2), *w2 = sym(g_w2);
    float *u1 = sym(g_u1), *v1 = sym(g_v1), *w1 = sym(g_w1);

    // ---- hypernetwork ----
    fc_small<<<(NB * 100 + 255) / 256, 256>>>(hyp, hw1, hb1, h1, 1, 100);
    fc_small<<<(NB * 1000 + 255) / 256, 256>>>(h1, hw2, hb2, h2, 100, 1000);
    fc_big<<<(10000 + 15) / 16, 256>>>(h2, hw3, hb3, ha, 1000, 10000, 1);
    fc_big<<<(10000 + 15) / 16, 256>>>(ha, hw4, hb4, hb, 10000, 10000, 1);
    fc_big<<<(10000 + 15) / 16, 256>>>(hb, hw5, hb5, ha, 10000, 10000, 1);
    fc_big<<<(OUTD  + 15) / 16, 256>>>(ha, hwo, hbo, fl, 10000, OUTD, 0);
    l1norm<<<NB, 256>>>(fl, dout, NB * HWI * HWI * 2);

    // ---- U-Net ----
    // weight offsets: w0=0 w1=144 w2=720 w3=1296 w4=1872 w5=2448 w6=3024 w7=3600
    //                 w8=4176 w9=5328 w10=5904 w11=7056 w12=7632 w13=8784 w14=9360
    dim3 blk(32, 8);
    dim3 g256(8, 32, NB), g128(4, 16, NB), g64(2, 8, NB), g32(1, 4, NB);

    conv3x3<2><<<g256, blk>>>(zf, t0, fl, 0,    WBASE_B + 0,   256, 256);
    conv3x3<8><<<g256, blk>>>(t0, c1, fl, 144,  WBASE_B + 8,   256, 256);
    maxpool2<<<(NB * 128 * 128 + 255) / 256, 256>>>(c1, p1, 128, 128);
    conv3x3<8><<<g128, blk>>>(p1, t1, fl, 720,  WBASE_B + 16,  128, 128);
    conv3x3<8><<<g128, blk>>>(t1, c2, fl, 1296, WBASE_B + 24,  128, 128);
    maxpool2<<<(NB * 64 * 64 + 255) / 256, 256>>>(c2, p2, 64, 64);
    conv3x3<8><<<g64, blk>>>(p2, t2, fl, 1872,  WBASE_B + 32,  64, 64);
    conv3x3<8><<<g64, blk>>>(t2, c3, fl, 2448,  WBASE_B + 40,  64, 64);
    maxpool2<<<(NB * 32 * 32 + 255) / 256, 256>>>(c3, p3, 32, 32);
    conv3x3<8><<<g32, blk>>>(p3, t3, fl, 3024,  WBASE_B + 48,  32, 32);
    conv3x3<8><<<g32, blk>>>(t3, c4, fl, 3600,  WBASE_B + 56,  32, 32);

    upcat<<<(NB * 64 * 64 + 255) / 256, 256>>>(c4, c3, u3, 32, 32);
    conv3x3<16><<<g64, blk>>>(u3, v3, fl, 4176, WBASE_B + 64,  64, 64);
    conv3x3<8><<<g64, blk>>>(v3, w3, fl, 5328,  WBASE_B + 72,  64, 64);

    upcat<<<(NB * 128 * 128 + 255) / 256, 256>>>(w3, c2, u2, 64, 64);
    conv3x3<16><<<g128, blk>>>(u2, v2, fl, 5904, WBASE_B + 80, 128, 128);
    conv3x3<8><<<g128, blk>>>(v2, w2, fl, 7056,  WBASE_B + 88, 128, 128);

    upcat<<<(NB * 256 * 256 + 255) / 256, 256>>>(w2, c1, u1, 128, 128);
    conv3x3<16><<<g256, blk>>>(u1, v1, fl, 7632, WBASE_B + 96, 256, 256);
    conv3x3<8><<<g256, blk>>>(v1, w1, fl, 8784,  WBASE_B + 104, 256, 256);

    conv1x1_res<<<(NB * HWI * HWI + 255) / 256, 256>>>(w1, zf, fl, dout);
}